// round 10
// baseline (speedup 1.0000x reference)
#include <cuda_runtime.h>
#include <math.h>

#define Bsz 128
#define Ssz 1024
#define Hsz 768
#define MAXV 25
#define NTOK 50                 // 2*MAXV
#define S_LEVI (Ssz - NTOK)     // 974

// ---- GEMM split-K config ----
#define KSPLIT 8                // 768 / 8 = 96 k per split
#define GTB 32                  // batches per block
#define GTH 128                 // h-outputs per block
#define GTK 32                  // k per smem tile
#define NITER 3                 // 96 / 32
#define WPAD 4                  // sW row pad

// Scratch (allocation-free rule: device globals)
__device__ float g_scores[Bsz * NTOK];
__device__ float g_pooled[Bsz * Hsz];
__device__ float g_part[KSPLIT * Bsz * Hsz];   // 3.1 MB partial sums

__device__ __forceinline__ float warp_sum(float v) {
#pragma unroll
    for (int o = 16; o > 0; o >>= 1) v += __shfl_xor_sync(0xffffffffu, v, o);
    return v;
}

// Detect verb_count dtype (int64 vs int32) and return v for batch b.
// 64 odd-word samples: all zero <=> int64 (values < 25), P(false hit) ~ 25^-64.
__device__ __forceinline__ int load_verb(const int* __restrict__ verb32,
                                         int b, int lane) {
    int a = verb32[2 * lane + 1];
    int c = verb32[2 * lane + 65];
    unsigned nz = __ballot_sync(0xffffffffu, (a | c) != 0);
    return nz ? verb32[b] : verb32[2 * b];
}

// ---------------------------------------------------------------------------
// Kernel 1a: scores. One 32-thread block per (token, batch); 6400 blocks.
// Inactive tokens write -inf and exit. Active: 768-wide dot vs align_w[H:2H].
// Subject-hidden term is a per-batch constant over active tokens; it cancels
// exactly in softmax, so it is skipped.
// ---------------------------------------------------------------------------
__global__ __launch_bounds__(32)
void score_kernel(const float* __restrict__ hidden,
                  const int*   __restrict__ verb32,
                  const float* __restrict__ align_w,   // [2H]
                  float*       __restrict__ scores)    // [B,NTOK]
{
    const int t    = blockIdx.x;
    const int b    = blockIdx.y;
    const int lane = threadIdx.x;

    const int v = load_verb(verb32, b, lane);
    const bool active = (t < v) || (t >= MAXV && t < MAXV + v);
    if (!active) {
        if (lane == 0) scores[b * NTOK + t] = -INFINITY;
        return;
    }

    const float4* __restrict__ row4 =
        (const float4*)(hidden + ((size_t)b * Ssz + S_LEVI + t) * Hsz);
    const float4* __restrict__ w4 = (const float4*)(align_w + Hsz);

    float4 a = make_float4(0.f, 0.f, 0.f, 0.f);
#pragma unroll
    for (int i = 0; i < 6; i++) {
        float4 hv = row4[lane + i * 32];
        float4 wv = w4[lane + i * 32];
        a.x = fmaf(hv.x, wv.x, a.x);
        a.y = fmaf(hv.y, wv.y, a.y);
        a.z = fmaf(hv.z, wv.z, a.z);
        a.w = fmaf(hv.w, wv.w, a.w);
    }
    float s = warp_sum((a.x + a.y) + (a.z + a.w));
    if (lane == 0) scores[b * NTOK + t] = s;
}

// ---------------------------------------------------------------------------
// Kernel 1b: softmax + weighted pooling. One block per batch, 256 threads.
// Active rows are L2-hot from score_kernel (whole 19.6 MB tail fits L2).
// ---------------------------------------------------------------------------
__global__ __launch_bounds__(256, 1)
void poolb_kernel(const float* __restrict__ hidden,
                  const int*   __restrict__ verb32,
                  const float* __restrict__ scores,   // [B,NTOK]
                  float*       __restrict__ pooled)   // [B,H]
{
    __shared__ float s_w[NTOK];   // weight per token slot t (0 if inactive)
    __shared__ int   s_v;

    const int b    = blockIdx.x;
    const int tid  = threadIdx.x;
    const int warp = tid >> 5;
    const int lane = tid & 31;

    if (warp == 0) {
        if (lane == 0) s_v = 0;
        int v = load_verb(verb32, b, lane);
        if (lane == 0) s_v = v;

        float a  = (lane < NTOK)      ? scores[b * NTOK + lane]      : -INFINITY;
        float b2 = (lane + 32 < NTOK) ? scores[b * NTOK + lane + 32] : -INFINITY;
        float m = fmaxf(a, b2);
#pragma unroll
        for (int o = 16; o > 0; o >>= 1)
            m = fmaxf(m, __shfl_xor_sync(0xffffffffu, m, o));
        if (!isfinite(m)) m = 0.f;
        float e1 = (a  > -INFINITY) ? expf(a  - m) : 0.f;
        float e2 = (b2 > -INFINITY) ? expf(b2 - m) : 0.f;
        float denom = warp_sum(e1 + e2);
        float inv = (denom > 0.f) ? (1.f / fmaxf(denom, 1e-30f)) : 0.f;
        if (lane < NTOK)      s_w[lane]      = e1 * inv;
        if (lane + 32 < NTOK) s_w[lane + 32] = e2 * inv;
    }
    __syncthreads();

    const int v    = s_v;
    const int nact = 2 * v;
    const float4* __restrict__ base4 =
        (const float4*)(hidden + ((size_t)b * Ssz + S_LEVI) * Hsz);

    // 192 threads: one float4 of H each. 4 token-parallel accumulators.
    if (tid < Hsz / 4) {
        float4 a0 = make_float4(0.f, 0.f, 0.f, 0.f);
        float4 a1 = make_float4(0.f, 0.f, 0.f, 0.f);
        float4 a2 = make_float4(0.f, 0.f, 0.f, 0.f);
        float4 a3 = make_float4(0.f, 0.f, 0.f, 0.f);
        int j = 0;
        for (; j + 4 <= nact; j += 4) {
            int t0 = (j + 0 < v) ? j + 0 : j + 0 - v + MAXV;
            int t1 = (j + 1 < v) ? j + 1 : j + 1 - v + MAXV;
            int t2 = (j + 2 < v) ? j + 2 : j + 2 - v + MAXV;
            int t3 = (j + 3 < v) ? j + 3 : j + 3 - v + MAXV;
            float w0 = s_w[t0], w1 = s_w[t1], w2 = s_w[t2], w3 = s_w[t3];
            float4 h0 = base4[(size_t)t0 * (Hsz / 4) + tid];
            float4 h1 = base4[(size_t)t1 * (Hsz / 4) + tid];
            float4 h2 = base4[(size_t)t2 * (Hsz / 4) + tid];
            float4 h3 = base4[(size_t)t3 * (Hsz / 4) + tid];
            a0.x = fmaf(w0, h0.x, a0.x); a0.y = fmaf(w0, h0.y, a0.y);
            a0.z = fmaf(w0, h0.z, a0.z); a0.w = fmaf(w0, h0.w, a0.w);
            a1.x = fmaf(w1, h1.x, a1.x); a1.y = fmaf(w1, h1.y, a1.y);
            a1.z = fmaf(w1, h1.z, a1.z); a1.w = fmaf(w1, h1.w, a1.w);
            a2.x = fmaf(w2, h2.x, a2.x); a2.y = fmaf(w2, h2.y, a2.y);
            a2.z = fmaf(w2, h2.z, a2.z); a2.w = fmaf(w2, h2.w, a2.w);
            a3.x = fmaf(w3, h3.x, a3.x); a3.y = fmaf(w3, h3.y, a3.y);
            a3.z = fmaf(w3, h3.z, a3.z); a3.w = fmaf(w3, h3.w, a3.w);
        }
        for (; j < nact; j++) {
            int t = (j < v) ? j : j - v + MAXV;
            float w = s_w[t];
            float4 hv = base4[(size_t)t * (Hsz / 4) + tid];
            a0.x = fmaf(w, hv.x, a0.x); a0.y = fmaf(w, hv.y, a0.y);
            a0.z = fmaf(w, hv.z, a0.z); a0.w = fmaf(w, hv.w, a0.w);
        }
        float4 r;
        r.x = (a0.x + a1.x) + (a2.x + a3.x);
        r.y = (a0.y + a1.y) + (a2.y + a3.y);
        r.z = (a0.z + a1.z) + (a2.z + a3.z);
        r.w = (a0.w + a1.w) + (a2.w + a3.w);
        ((float4*)pooled)[(size_t)b * (Hsz / 4) + tid] = r;
    }
}

// ---------------------------------------------------------------------------
// Kernel 2: split-K partial GEMM. part[z][b][h] = sum_{k in split z} P[b,k]*W[h,k]
// grid = (6, 4, 8) = 192 blocks, 256 threads, 4b x 4h register tile,
// double-buffered smem with register prefetch.
// ---------------------------------------------------------------------------
__global__ __launch_bounds__(256, 1)
void gemm_partial(const float* __restrict__ P,     // [B,H] pooled
                  const float* __restrict__ W,     // [H,H] out_w (k contiguous)
                  float*       __restrict__ part)  // [KSPLIT,B,H]
{
    __shared__ float sP[2][GTB][GTK];          // 8 KB
    __shared__ float sW[2][GTK][GTH + WPAD];   // 33.8 KB (k-major, padded)

    const int tid  = threadIdx.x;
    const int wid  = tid >> 5;
    const int lane = tid & 31;
    const int h0   = blockIdx.x * GTH;
    const int b0   = blockIdx.y * GTB;
    const int ks0  = blockIdx.z * (Hsz / KSPLIT);

    const int pr  = tid >> 3;
    const int pc4 = tid & 7;

    float4 pre_p;
    float4 pre_w[4];

    {
        const int kk = ks0;
        pre_p = *(const float4*)&P[(size_t)(b0 + pr) * Hsz + kk + pc4 * 4];
#pragma unroll
        for (int i = 0; i < 4; i++) {
            int q  = tid + i * 256;
            int hh = q >> 3, c4 = q & 7;
            pre_w[i] = *(const float4*)&W[(size_t)(h0 + hh) * Hsz + kk + c4 * 4];
        }
    }
    {
        *(float4*)&sP[0][pr][pc4 * 4] = pre_p;
#pragma unroll
        for (int i = 0; i < 4; i++) {
            int q  = tid + i * 256;
            int hh = q >> 3, c4 = q & 7;
            sW[0][c4 * 4 + 0][hh] = pre_w[i].x;
            sW[0][c4 * 4 + 1][hh] = pre_w[i].y;
            sW[0][c4 * 4 + 2][hh] = pre_w[i].z;
            sW[0][c4 * 4 + 3][hh] = pre_w[i].w;
        }
    }
    __syncthreads();

    float4 acc[4];
#pragma unroll
    for (int j = 0; j < 4; j++) acc[j] = make_float4(0.f, 0.f, 0.f, 0.f);

#pragma unroll
    for (int it = 0; it < NITER; it++) {
        const int cur = it & 1;

        if (it < NITER - 1) {
            const int kk = ks0 + (it + 1) * GTK;
            pre_p = *(const float4*)&P[(size_t)(b0 + pr) * Hsz + kk + pc4 * 4];
#pragma unroll
            for (int i = 0; i < 4; i++) {
                int q  = tid + i * 256;
                int hh = q >> 3, c4 = q & 7;
                pre_w[i] = *(const float4*)&W[(size_t)(h0 + hh) * Hsz + kk + c4 * 4];
            }
        }

#pragma unroll
        for (int k = 0; k < GTK; k++) {
            float4 wv = *(const float4*)&sW[cur][k][lane * 4];
            float p0 = sP[cur][wid * 4 + 0][k];
            float p1 = sP[cur][wid * 4 + 1][k];
            float p2 = sP[cur][wid * 4 + 2][k];
            float p3 = sP[cur][wid * 4 + 3][k];
            acc[0].x = fmaf(p0, wv.x, acc[0].x); acc[0].y = fmaf(p0, wv.y, acc[0].y);
            acc[0].z = fmaf(p0, wv.z, acc[0].z); acc[0].w = fmaf(p0, wv.w, acc[0].w);
            acc[1].x = fmaf(p1, wv.x, acc[1].x); acc[1].y = fmaf(p1, wv.y, acc[1].y);
            acc[1].z = fmaf(p1, wv.z, acc[1].z); acc[1].w = fmaf(p1, wv.w, acc[1].w);
            acc[2].x = fmaf(p2, wv.x, acc[2].x); acc[2].y = fmaf(p2, wv.y, acc[2].y);
            acc[2].z = fmaf(p2, wv.z, acc[2].z); acc[2].w = fmaf(p2, wv.w, acc[2].w);
            acc[3].x = fmaf(p3, wv.x, acc[3].x); acc[3].y = fmaf(p3, wv.y, acc[3].y);
            acc[3].z = fmaf(p3, wv.z, acc[3].z); acc[3].w = fmaf(p3, wv.w, acc[3].w);
        }

        if (it < NITER - 1) {
            __syncthreads();
            const int nxt = cur ^ 1;
            *(float4*)&sP[nxt][pr][pc4 * 4] = pre_p;
#pragma unroll
            for (int i = 0; i < 4; i++) {
                int q  = tid + i * 256;
                int hh = q >> 3, c4 = q & 7;
                sW[nxt][c4 * 4 + 0][hh] = pre_w[i].x;
                sW[nxt][c4 * 4 + 1][hh] = pre_w[i].y;
                sW[nxt][c4 * 4 + 2][hh] = pre_w[i].z;
                sW[nxt][c4 * 4 + 3][hh] = pre_w[i].w;
            }
            __syncthreads();
        }
    }

    float* base = part + ((size_t)blockIdx.z * Bsz) * Hsz;
#pragma unroll
    for (int j = 0; j < 4; j++) {
        *(float4*)&base[(size_t)(b0 + wid * 4 + j) * Hsz + h0 + lane * 4] = acc[j];
    }
}

// ---------------------------------------------------------------------------
// Kernel 3: epilogue. out[b,h] = tanh( sum_z part[z][b][h] + bias[h] )
// ---------------------------------------------------------------------------
__global__ __launch_bounds__(256)
void epilogue(const float* __restrict__ part,
              const float* __restrict__ bias,
              float*       __restrict__ out)
{
    const int idx = blockIdx.x * 256 + threadIdx.x;
    const float4* p4 = (const float4*)part;
    const int b  = idx / (Hsz / 4);
    const int h4 = idx % (Hsz / 4);

    float4 s = make_float4(0.f, 0.f, 0.f, 0.f);
#pragma unroll
    for (int z = 0; z < KSPLIT; z++) {
        float4 v = p4[(size_t)(z * Bsz + b) * (Hsz / 4) + h4];
        s.x += v.x; s.y += v.y; s.z += v.z; s.w += v.w;
    }
    float4 bi = ((const float4*)bias)[h4];
    float4 o;
    o.x = tanhf(s.x + bi.x);
    o.y = tanhf(s.y + bi.y);
    o.z = tanhf(s.z + bi.z);
    o.w = tanhf(s.w + bi.w);
    ((float4*)out)[idx] = o;
}

// ---------------------------------------------------------------------------
extern "C" void kernel_launch(void* const* d_in, const int* in_sizes, int n_in,
                              void* d_out, int out_size)
{
    const float* hidden   = (const float*)d_in[0];
    const int*   verb32   = (const int*)  d_in[1];  // int32 view; dtype auto-detected
    const float* align_w  = (const float*)d_in[3];
    const float* out_w    = (const float*)d_in[5];
    const float* out_b    = (const float*)d_in[6];
    float* out = (float*)d_out;

    float* scores = nullptr;
    float* pooled = nullptr;
    float* part   = nullptr;
    cudaGetSymbolAddress((void**)&scores, g_scores);
    cudaGetSymbolAddress((void**)&pooled, g_pooled);
    cudaGetSymbolAddress((void**)&part,   g_part);

    score_kernel<<<dim3(NTOK, Bsz), 32>>>(hidden, verb32, align_w, scores);
    poolb_kernel<<<Bsz, 256>>>(hidden, verb32, scores, pooled);
    gemm_partial<<<dim3(Hsz / GTH, Bsz / GTB, KSPLIT), 256>>>(pooled, out_w, part);
    epilogue<<<(Bsz * Hsz / 4) / 256, 256>>>(part, out_b, out);
}

// round 11
// speedup vs baseline: 1.1099x; 1.1099x over previous
#include <cuda_runtime.h>
#include <math.h>

#define Bsz 128
#define Ssz 1024
#define Hsz 768
#define MAXV 25
#define NTOK 50                 // 2*MAXV
#define S_LEVI (Ssz - NTOK)     // 974
#define H4 (Hsz / 4)            // 192 float4 per row

// ---- GEMM split-K config ----
#define KSPLIT 8                // 768 / 8 = 96 k per split
#define GTB 32                  // batches per block
#define GTH 128                 // h-outputs per block
#define GTK 32                  // k per smem tile
#define NITER 3                 // 96 / 32
#define WPAD 4                  // sW row pad
#define NTILE ((Bsz / GTB) * (Hsz / GTH))   // 24 output tiles

// Scratch (allocation-free rule: device globals)
__device__ float g_pooled[Bsz * Hsz];
__device__ float g_part[KSPLIT * Bsz * Hsz];   // 3.1 MB partial sums
__device__ int   g_cnt[NTILE];                 // zero-init; reset by last block

__device__ __forceinline__ float warp_sum(float v) {
#pragma unroll
    for (int o = 16; o > 0; o >>= 1) v += __shfl_xor_sync(0xffffffffu, v, o);
    return v;
}

// Detect verb_count dtype (int64 vs int32) and return v for batch b.
// 64 odd-word samples all zero <=> int64 (values < 25). Warp-collective.
__device__ __forceinline__ int load_verb(const int* __restrict__ verb32,
                                         int b, int lane) {
    int a = verb32[2 * lane + 1];
    int c = verb32[2 * lane + 65];
    unsigned nz = __ballot_sync(0xffffffffu, (a | c) != 0);
    return nz ? verb32[b] : verb32[2 * b];
}

// ---------------------------------------------------------------------------
// Kernel 1: fused masked-attention pooling. One block per batch, 768 threads.
// Active ordinals j in [0,2v): token t = j<v ? j : j-v+MAXV. Inactive rows
// have weight exactly 0 in the reference and are never touched. The
// subject-hidden score term is a per-batch constant over active tokens and
// cancels exactly in softmax; skipped.
// ---------------------------------------------------------------------------
__global__ __launch_bounds__(768, 1)
void pool_kernel(const float* __restrict__ hidden,
                 const int*   __restrict__ verb32,
                 const float* __restrict__ align_w,   // [2H]
                 float*       __restrict__ pooled)    // [B,H]
{
    __shared__ float  s_scores[NTOK];     // by active ordinal j
    __shared__ float  s_wact[NTOK];       // weight of ordinal j
    __shared__ float4 s_part[4][H4];      // 12 KB cross-group pooling partials

    const int b    = blockIdx.x;
    const int tid  = threadIdx.x;
    const int warp = tid >> 5;
    const int lane = tid & 31;

    const int v    = load_verb(verb32, b, lane);   // warp-uniform
    const int nact = 2 * v;

    if (tid < NTOK) s_scores[tid] = -INFINITY;
    __syncthreads();

    const float* __restrict__ bbase = hidden + ((size_t)b * Ssz + S_LEVI) * Hsz;
    const float4* __restrict__ base4 = (const float4*)bbase;
    const float4* __restrict__ w4    = (const float4*)(align_w + Hsz);

    // --- pass 1: scores, warp per active ordinal (24 warps, <=2 rounds) ---
    for (int j = warp; j < nact; j += 24) {
        const int t = (j < v) ? j : (j - v + MAXV);
        const float4* row4 = base4 + (size_t)t * H4;
        float4 a = make_float4(0.f, 0.f, 0.f, 0.f);
#pragma unroll
        for (int i = 0; i < 6; i++) {
            float4 hv = row4[lane + i * 32];
            float4 wv = w4[lane + i * 32];
            a.x = fmaf(hv.x, wv.x, a.x);
            a.y = fmaf(hv.y, wv.y, a.y);
            a.z = fmaf(hv.z, wv.z, a.z);
            a.w = fmaf(hv.w, wv.w, a.w);
        }
        float s = warp_sum((a.x + a.y) + (a.z + a.w));
        if (lane == 0) s_scores[j] = s;
    }
    __syncthreads();

    // --- pass 2: softmax over ordinals (warp 0) ---
    if (warp == 0) {
        float a  = (lane < NTOK)      ? s_scores[lane]      : -INFINITY;
        float b2 = (lane + 32 < NTOK) ? s_scores[lane + 32] : -INFINITY;
        float m = fmaxf(a, b2);
#pragma unroll
        for (int o = 16; o > 0; o >>= 1)
            m = fmaxf(m, __shfl_xor_sync(0xffffffffu, m, o));
        if (!isfinite(m)) m = 0.f;
        float e1 = (a  > -INFINITY) ? expf(a  - m) : 0.f;
        float e2 = (b2 > -INFINITY) ? expf(b2 - m) : 0.f;
        float denom = warp_sum(e1 + e2);
        float inv = (denom > 0.f) ? (1.f / fmaxf(denom, 1e-30f)) : 0.f;
        if (lane < NTOK)      s_wact[lane]      = e1 * inv;
        if (lane + 32 < NTOK) s_wact[lane + 32] = e2 * inv;
    }
    __syncthreads();

    // --- pass 3: pooled, (4 token-groups x 192 h-chunks) then smem reduce ---
    {
        const int grp = tid / H4;     // 0..3
        const int h4  = tid % H4;     // 0..191
        float4 acc = make_float4(0.f, 0.f, 0.f, 0.f);
#pragma unroll 2
        for (int j = grp; j < nact; j += 4) {
            const int t = (j < v) ? j : (j - v + MAXV);
            const float w = s_wact[j];
            float4 hv = base4[(size_t)t * H4 + h4];
            acc.x = fmaf(w, hv.x, acc.x);
            acc.y = fmaf(w, hv.y, acc.y);
            acc.z = fmaf(w, hv.z, acc.z);
            acc.w = fmaf(w, hv.w, acc.w);
        }
        s_part[grp][h4] = acc;
    }
    __syncthreads();

    if (tid < H4) {
        float4 p0 = s_part[0][tid], p1 = s_part[1][tid];
        float4 p2 = s_part[2][tid], p3 = s_part[3][tid];
        float4 r;
        r.x = (p0.x + p1.x) + (p2.x + p3.x);
        r.y = (p0.y + p1.y) + (p2.y + p3.y);
        r.z = (p0.z + p1.z) + (p2.z + p3.z);
        r.w = (p0.w + p1.w) + (p2.w + p3.w);
        ((float4*)pooled)[(size_t)b * H4 + tid] = r;
    }
}

// ---------------------------------------------------------------------------
// Kernel 2: split-K GEMM with fused reduction+bias+tanh (last block per
// output tile reduces). part[z][b][h] = sum_{k in split z} P[b,k]*W[h,k];
// last arriving z-block for a tile sums z=0..7 in fixed order (deterministic),
// adds bias, tanh, writes out. Counter reset in-kernel for graph replays.
// grid = (6, 4, 8) = 192 blocks, 256 threads, 4b x 4h register tile.
// ---------------------------------------------------------------------------
__global__ __launch_bounds__(256, 1)
void gemm_fused(const float* __restrict__ P,     // [B,H] pooled
                const float* __restrict__ W,     // [H,H] out_w (k contiguous)
                const float* __restrict__ bias,  // [H]
                float*       __restrict__ part,  // [KSPLIT,B,H] scratch
                float*       __restrict__ out)   // [B,H]
{
    __shared__ float sP[2][GTB][GTK];          // 8 KB
    __shared__ float sW[2][GTK][GTH + WPAD];   // 33.8 KB (k-major, padded)
    __shared__ int   s_last;

    const int tid  = threadIdx.x;
    const int wid  = tid >> 5;
    const int lane = tid & 31;
    const int h0   = blockIdx.x * GTH;
    const int b0   = blockIdx.y * GTB;
    const int ks0  = blockIdx.z * (Hsz / KSPLIT);
    const int tileId = blockIdx.y * gridDim.x + blockIdx.x;

    const int pr  = tid >> 3;
    const int pc4 = tid & 7;

    float4 pre_p;
    float4 pre_w[4];

    {
        const int kk = ks0;
        pre_p = *(const float4*)&P[(size_t)(b0 + pr) * Hsz + kk + pc4 * 4];
#pragma unroll
        for (int i = 0; i < 4; i++) {
            int q  = tid + i * 256;
            int hh = q >> 3, c4 = q & 7;
            pre_w[i] = *(const float4*)&W[(size_t)(h0 + hh) * Hsz + kk + c4 * 4];
        }
    }
    {
        *(float4*)&sP[0][pr][pc4 * 4] = pre_p;
#pragma unroll
        for (int i = 0; i < 4; i++) {
            int q  = tid + i * 256;
            int hh = q >> 3, c4 = q & 7;
            sW[0][c4 * 4 + 0][hh] = pre_w[i].x;
            sW[0][c4 * 4 + 1][hh] = pre_w[i].y;
            sW[0][c4 * 4 + 2][hh] = pre_w[i].z;
            sW[0][c4 * 4 + 3][hh] = pre_w[i].w;
        }
    }
    __syncthreads();

    float4 acc[4];
#pragma unroll
    for (int j = 0; j < 4; j++) acc[j] = make_float4(0.f, 0.f, 0.f, 0.f);

#pragma unroll
    for (int it = 0; it < NITER; it++) {
        const int cur = it & 1;

        if (it < NITER - 1) {
            const int kk = ks0 + (it + 1) * GTK;
            pre_p = *(const float4*)&P[(size_t)(b0 + pr) * Hsz + kk + pc4 * 4];
#pragma unroll
            for (int i = 0; i < 4; i++) {
                int q  = tid + i * 256;
                int hh = q >> 3, c4 = q & 7;
                pre_w[i] = *(const float4*)&W[(size_t)(h0 + hh) * Hsz + kk + c4 * 4];
            }
        }

#pragma unroll
        for (int k = 0; k < GTK; k++) {
            float4 wv = *(const float4*)&sW[cur][k][lane * 4];
            float p0 = sP[cur][wid * 4 + 0][k];
            float p1 = sP[cur][wid * 4 + 1][k];
            float p2 = sP[cur][wid * 4 + 2][k];
            float p3 = sP[cur][wid * 4 + 3][k];
            acc[0].x = fmaf(p0, wv.x, acc[0].x); acc[0].y = fmaf(p0, wv.y, acc[0].y);
            acc[0].z = fmaf(p0, wv.z, acc[0].z); acc[0].w = fmaf(p0, wv.w, acc[0].w);
            acc[1].x = fmaf(p1, wv.x, acc[1].x); acc[1].y = fmaf(p1, wv.y, acc[1].y);
            acc[1].z = fmaf(p1, wv.z, acc[1].z); acc[1].w = fmaf(p1, wv.w, acc[1].w);
            acc[2].x = fmaf(p2, wv.x, acc[2].x); acc[2].y = fmaf(p2, wv.y, acc[2].y);
            acc[2].z = fmaf(p2, wv.z, acc[2].z); acc[2].w = fmaf(p2, wv.w, acc[2].w);
            acc[3].x = fmaf(p3, wv.x, acc[3].x); acc[3].y = fmaf(p3, wv.y, acc[3].y);
            acc[3].z = fmaf(p3, wv.z, acc[3].z); acc[3].w = fmaf(p3, wv.w, acc[3].w);
        }

        if (it < NITER - 1) {
            __syncthreads();
            const int nxt = cur ^ 1;
            *(float4*)&sP[nxt][pr][pc4 * 4] = pre_p;
#pragma unroll
            for (int i = 0; i < 4; i++) {
                int q  = tid + i * 256;
                int hh = q >> 3, c4 = q & 7;
                sW[nxt][c4 * 4 + 0][hh] = pre_w[i].x;
                sW[nxt][c4 * 4 + 1][hh] = pre_w[i].y;
                sW[nxt][c4 * 4 + 2][hh] = pre_w[i].z;
                sW[nxt][c4 * 4 + 3][hh] = pre_w[i].w;
            }
            __syncthreads();
        }
    }

    // store this split's partials
    {
        float* base = part + ((size_t)blockIdx.z * Bsz) * Hsz;
#pragma unroll
        for (int j = 0; j < 4; j++) {
            *(float4*)&base[(size_t)(b0 + wid * 4 + j) * Hsz + h0 + lane * 4]
                = acc[j];
        }
    }

    // --- last-block-reduces (threadFenceReduction pattern) ---
    __threadfence();
    if (tid == 0) {
        int old = atomicAdd(&g_cnt[tileId], 1);
        int last = (old == KSPLIT - 1);
        if (last) g_cnt[tileId] = 0;   // reset for next graph replay
        s_last = last;
    }
    __syncthreads();
    if (!s_last) return;

    // reduce this tile: each thread its own 4 (b,h4) slots, z in fixed order
    const int hb = h0 + lane * 4;
    const float4 bi = *(const float4*)&bias[hb];
#pragma unroll
    for (int j = 0; j < 4; j++) {
        const size_t off = (size_t)(b0 + wid * 4 + j) * Hsz + hb;
        float4 s = make_float4(0.f, 0.f, 0.f, 0.f);
#pragma unroll
        for (int z = 0; z < KSPLIT; z++) {
            float4 pv = *(const float4*)&part[(size_t)z * Bsz * Hsz + off];
            s.x += pv.x; s.y += pv.y; s.z += pv.z; s.w += pv.w;
        }
        float4 o;
        o.x = tanhf(s.x + bi.x);
        o.y = tanhf(s.y + bi.y);
        o.z = tanhf(s.z + bi.z);
        o.w = tanhf(s.w + bi.w);
        *(float4*)&out[off] = o;
    }
}

// ---------------------------------------------------------------------------
extern "C" void kernel_launch(void* const* d_in, const int* in_sizes, int n_in,
                              void* d_out, int out_size)
{
    const float* hidden   = (const float*)d_in[0];
    const int*   verb32   = (const int*)  d_in[1];  // int32 view; dtype auto-detected
    const float* align_w  = (const float*)d_in[3];
    const float* out_w    = (const float*)d_in[5];
    const float* out_b    = (const float*)d_in[6];
    float* out = (float*)d_out;

    float* pooled = nullptr;
    float* part   = nullptr;
    cudaGetSymbolAddress((void**)&pooled, g_pooled);
    cudaGetSymbolAddress((void**)&part,   g_part);

    pool_kernel<<<Bsz, 768>>>(hidden, verb32, align_w, pooled);
    gemm_fused<<<dim3(Hsz / GTH, Bsz / GTB, KSPLIT), 256>>>(pooled, out_w,
                                                            out_b, part, out);
}

// round 12
// speedup vs baseline: 1.2280x; 1.1064x over previous
#include <cuda_runtime.h>
#include <math.h>

#define Bsz 128
#define Ssz 1024
#define Hsz 768
#define MAXV 25
#define NTOK 50                 // 2*MAXV
#define S_LEVI (Ssz - NTOK)     // 974
#define H4 (Hsz / 4)            // 192 float4 per row

// ---- GEMM split-K config (R12: smaller tiles, 2x blocks, fewer regs) ----
#define KSPLIT 8                // 768 / 8 = 96 k per split
#define GTB 32                  // batches per block
#define GTH 64                  // h-outputs per block
#define GTK 32                  // k per smem tile
#define NITER 3                 // 96 / 32
#define WPAD 4                  // sW row pad
#define NTILE ((Bsz / GTB) * (Hsz / GTH))   // 48 output tiles

// Scratch (allocation-free rule: device globals)
__device__ float g_pooled[Bsz * Hsz];
__device__ float g_part[KSPLIT * Bsz * Hsz];   // 3.1 MB partial sums
__device__ int   g_cnt[NTILE];                 // zero-init; reset by last block

__device__ __forceinline__ float warp_sum(float v) {
#pragma unroll
    for (int o = 16; o > 0; o >>= 1) v += __shfl_xor_sync(0xffffffffu, v, o);
    return v;
}

// Detect verb_count dtype (int64 vs int32) and return v for batch b.
// 64 odd-word samples all zero <=> int64 (values < 25). Warp-collective.
__device__ __forceinline__ int load_verb(const int* __restrict__ verb32,
                                         int b, int lane) {
    int a = verb32[2 * lane + 1];
    int c = verb32[2 * lane + 65];
    unsigned nz = __ballot_sync(0xffffffffu, (a | c) != 0);
    return nz ? verb32[b] : verb32[2 * b];
}

// ---------------------------------------------------------------------------
// Kernel 1: fused masked-attention pooling. One block per batch, 768 threads.
// Active ordinals j in [0,2v): token t = j<v ? j : j-v+MAXV. Inactive rows
// have weight exactly 0 in the reference and are never touched. The
// subject-hidden score term is a per-batch constant over active tokens and
// cancels exactly in softmax; skipped.
// ---------------------------------------------------------------------------
__global__ __launch_bounds__(768, 1)
void pool_kernel(const float* __restrict__ hidden,
                 const int*   __restrict__ verb32,
                 const float* __restrict__ align_w,   // [2H]
                 float*       __restrict__ pooled)    // [B,H]
{
    __shared__ float  s_scores[NTOK];     // by active ordinal j
    __shared__ float  s_wact[NTOK];       // weight of ordinal j
    __shared__ float4 s_part[4][H4];      // 12 KB cross-group pooling partials

    const int b    = blockIdx.x;
    const int tid  = threadIdx.x;
    const int warp = tid >> 5;
    const int lane = tid & 31;

    const int v    = load_verb(verb32, b, lane);   // warp-uniform
    const int nact = 2 * v;

    if (tid < NTOK) s_scores[tid] = -INFINITY;
    __syncthreads();

    const float* __restrict__ bbase = hidden + ((size_t)b * Ssz + S_LEVI) * Hsz;
    const float4* __restrict__ base4 = (const float4*)bbase;
    const float4* __restrict__ w4    = (const float4*)(align_w + Hsz);

    // --- pass 1: scores, warp per active ordinal (24 warps, <=2 rounds) ---
    for (int j = warp; j < nact; j += 24) {
        const int t = (j < v) ? j : (j - v + MAXV);
        const float4* row4 = base4 + (size_t)t * H4;
        float4 a = make_float4(0.f, 0.f, 0.f, 0.f);
#pragma unroll
        for (int i = 0; i < 6; i++) {
            float4 hv = row4[lane + i * 32];
            float4 wv = w4[lane + i * 32];
            a.x = fmaf(hv.x, wv.x, a.x);
            a.y = fmaf(hv.y, wv.y, a.y);
            a.z = fmaf(hv.z, wv.z, a.z);
            a.w = fmaf(hv.w, wv.w, a.w);
        }
        float s = warp_sum((a.x + a.y) + (a.z + a.w));
        if (lane == 0) s_scores[j] = s;
    }
    __syncthreads();

    // --- pass 2: softmax over ordinals (warp 0) ---
    if (warp == 0) {
        float a  = (lane < NTOK)      ? s_scores[lane]      : -INFINITY;
        float b2 = (lane + 32 < NTOK) ? s_scores[lane + 32] : -INFINITY;
        float m = fmaxf(a, b2);
#pragma unroll
        for (int o = 16; o > 0; o >>= 1)
            m = fmaxf(m, __shfl_xor_sync(0xffffffffu, m, o));
        if (!isfinite(m)) m = 0.f;
        float e1 = (a  > -INFINITY) ? expf(a  - m) : 0.f;
        float e2 = (b2 > -INFINITY) ? expf(b2 - m) : 0.f;
        float denom = warp_sum(e1 + e2);
        float inv = (denom > 0.f) ? (1.f / fmaxf(denom, 1e-30f)) : 0.f;
        if (lane < NTOK)      s_wact[lane]      = e1 * inv;
        if (lane + 32 < NTOK) s_wact[lane + 32] = e2 * inv;
    }
    __syncthreads();

    // --- pass 3: pooled, (4 token-groups x 192 h-chunks) then smem reduce ---
    {
        const int grp = tid / H4;     // 0..3
        const int h4  = tid % H4;     // 0..191
        float4 acc = make_float4(0.f, 0.f, 0.f, 0.f);
#pragma unroll 2
        for (int j = grp; j < nact; j += 4) {
            const int t = (j < v) ? j : (j - v + MAXV);
            const float w = s_wact[j];
            float4 hv = base4[(size_t)t * H4 + h4];
            acc.x = fmaf(w, hv.x, acc.x);
            acc.y = fmaf(w, hv.y, acc.y);
            acc.z = fmaf(w, hv.z, acc.z);
            acc.w = fmaf(w, hv.w, acc.w);
        }
        s_part[grp][h4] = acc;
    }
    __syncthreads();

    if (tid < H4) {
        float4 p0 = s_part[0][tid], p1 = s_part[1][tid];
        float4 p2 = s_part[2][tid], p3 = s_part[3][tid];
        float4 r;
        r.x = (p0.x + p1.x) + (p2.x + p3.x);
        r.y = (p0.y + p1.y) + (p2.y + p3.y);
        r.z = (p0.z + p1.z) + (p2.z + p3.z);
        r.w = (p0.w + p1.w) + (p2.w + p3.w);
        ((float4*)pooled)[(size_t)b * H4 + tid] = r;
    }
}

// ---------------------------------------------------------------------------
// Kernel 2: split-K GEMM, 32b x 64h tiles, grid (12,4,8)=384 blocks,
// 256 threads, 2b x 4h per-thread microtile. Fused deterministic
// last-block reduction + bias + tanh (threadFenceReduction pattern,
// counter self-reset for graph replay).
// ---------------------------------------------------------------------------
__global__ __launch_bounds__(256, 3)
void gemm_fused(const float* __restrict__ P,     // [B,H] pooled
                const float* __restrict__ W,     // [H,H] out_w (k contiguous)
                const float* __restrict__ bias,  // [H]
                float*       __restrict__ part,  // [KSPLIT,B,H] scratch
                float*       __restrict__ out)   // [B,H]
{
    __shared__ float sP[2][GTB][GTK];          // 8 KB
    __shared__ float sW[2][GTK][GTH + WPAD];   // 17.4 KB (k-major, padded)
    __shared__ int   s_last;

    const int tid  = threadIdx.x;
    const int h0   = blockIdx.x * GTH;
    const int b0   = blockIdx.y * GTB;
    const int ks0  = blockIdx.z * (Hsz / KSPLIT);
    const int tileId = blockIdx.y * gridDim.x + blockIdx.x;

    // compute mapping: 2 rows {r, r+16}, 4 cols at c4*4
    const int r  = tid >> 4;            // 0..15
    const int c4 = tid & 15;            // 0..15

    // tile-load mapping
    const int pr  = tid >> 3;           // 0..31  P row
    const int pc4 = tid & 7;            // 0..7   P float4 col

    float4 pre_p;
    float4 pre_w[2];

    // prefetch tile 0
    {
        const int kk = ks0;
        pre_p = *(const float4*)&P[(size_t)(b0 + pr) * Hsz + kk + pc4 * 4];
#pragma unroll
        for (int i = 0; i < 2; i++) {
            int q  = tid + i * 256;
            int hh = q >> 3, cc = q & 7;
            pre_w[i] = *(const float4*)&W[(size_t)(h0 + hh) * Hsz + kk + cc * 4];
        }
    }
    {
        *(float4*)&sP[0][pr][pc4 * 4] = pre_p;
#pragma unroll
        for (int i = 0; i < 2; i++) {
            int q  = tid + i * 256;
            int hh = q >> 3, cc = q & 7;
            sW[0][cc * 4 + 0][hh] = pre_w[i].x;
            sW[0][cc * 4 + 1][hh] = pre_w[i].y;
            sW[0][cc * 4 + 2][hh] = pre_w[i].z;
            sW[0][cc * 4 + 3][hh] = pre_w[i].w;
        }
    }
    __syncthreads();

    float4 acc0 = make_float4(0.f, 0.f, 0.f, 0.f);
    float4 acc1 = make_float4(0.f, 0.f, 0.f, 0.f);

#pragma unroll
    for (int it = 0; it < NITER; it++) {
        const int cur = it & 1;

        if (it < NITER - 1) {
            const int kk = ks0 + (it + 1) * GTK;
            pre_p = *(const float4*)&P[(size_t)(b0 + pr) * Hsz + kk + pc4 * 4];
#pragma unroll
            for (int i = 0; i < 2; i++) {
                int q  = tid + i * 256;
                int hh = q >> 3, cc = q & 7;
                pre_w[i] = *(const float4*)&W[(size_t)(h0 + hh) * Hsz + kk + cc * 4];
            }
        }

#pragma unroll
        for (int k = 0; k < GTK; k++) {
            float4 wv = *(const float4*)&sW[cur][k][c4 * 4];
            float p0 = sP[cur][r][k];
            float p1 = sP[cur][r + 16][k];
            acc0.x = fmaf(p0, wv.x, acc0.x); acc0.y = fmaf(p0, wv.y, acc0.y);
            acc0.z = fmaf(p0, wv.z, acc0.z); acc0.w = fmaf(p0, wv.w, acc0.w);
            acc1.x = fmaf(p1, wv.x, acc1.x); acc1.y = fmaf(p1, wv.y, acc1.y);
            acc1.z = fmaf(p1, wv.z, acc1.z); acc1.w = fmaf(p1, wv.w, acc1.w);
        }

        if (it < NITER - 1) {
            __syncthreads();
            const int nxt = cur ^ 1;
            *(float4*)&sP[nxt][pr][pc4 * 4] = pre_p;
#pragma unroll
            for (int i = 0; i < 2; i++) {
                int q  = tid + i * 256;
                int hh = q >> 3, cc = q & 7;
                sW[nxt][cc * 4 + 0][hh] = pre_w[i].x;
                sW[nxt][cc * 4 + 1][hh] = pre_w[i].y;
                sW[nxt][cc * 4 + 2][hh] = pre_w[i].z;
                sW[nxt][cc * 4 + 3][hh] = pre_w[i].w;
            }
            __syncthreads();
        }
    }

    // store this split's partials
    {
        float* base = part + ((size_t)blockIdx.z * Bsz) * Hsz;
        *(float4*)&base[(size_t)(b0 + r)      * Hsz + h0 + c4 * 4] = acc0;
        *(float4*)&base[(size_t)(b0 + r + 16) * Hsz + h0 + c4 * 4] = acc1;
    }

    // --- last-block-reduces (threadFenceReduction pattern) ---
    __threadfence();
    if (tid == 0) {
        int old = atomicAdd(&g_cnt[tileId], 1);
        int last = (old == KSPLIT - 1);
        if (last) g_cnt[tileId] = 0;   // reset for next graph replay
        s_last = last;
    }
    __syncthreads();
    if (!s_last) return;

    // reduce this tile: each thread its 2 (b,h4) slots, z in fixed order
    const int hb = h0 + c4 * 4;
    const float4 bi = *(const float4*)&bias[hb];
#pragma unroll
    for (int j = 0; j < 2; j++) {
        const size_t off = (size_t)(b0 + r + j * 16) * Hsz + hb;
        float4 s = make_float4(0.f, 0.f, 0.f, 0.f);
#pragma unroll
        for (int z = 0; z < KSPLIT; z++) {
            float4 pv = *(const float4*)&part[(size_t)z * Bsz * Hsz + off];
            s.x += pv.x; s.y += pv.y; s.z += pv.z; s.w += pv.w;
        }
        float4 o;
        o.x = tanhf(s.x + bi.x);
        o.y = tanhf(s.y + bi.y);
        o.z = tanhf(s.z + bi.z);
        o.w = tanhf(s.w + bi.w);
        *(float4*)&out[off] = o;
    }
}

// ---------------------------------------------------------------------------
extern "C" void kernel_launch(void* const* d_in, const int* in_sizes, int n_in,
                              void* d_out, int out_size)
{
    const float* hidden   = (const float*)d_in[0];
    const int*   verb32   = (const int*)  d_in[1];  // int32 view; dtype auto-detected
    const float* align_w  = (const float*)d_in[3];
    const float* out_w    = (const float*)d_in[5];
    const float* out_b    = (const float*)d_in[6];
    float* out = (float*)d_out;

    float* pooled = nullptr;
    float* part   = nullptr;
    cudaGetSymbolAddress((void**)&pooled, g_pooled);
    cudaGetSymbolAddress((void**)&part,   g_part);

    pool_kernel<<<Bsz, 768>>>(hidden, verb32, align_w, pooled);
    gemm_fused<<<dim3(Hsz / GTH, Bsz / GTB, KSPLIT), 256>>>(pooled, out_w,
                                                            out_b, part, out);
}